// round 16
// baseline (speedup 1.0000x reference)
#include <cuda_runtime.h>
#include <cuda_fp16.h>
#include <cstdint>

#define T_TOK 8192
#define DIM   1024
#define HID   2048
#define NE    8
#define BM    128
#define BN    128
#define BK    64
#define RCAP  (T_TOK*2 + NE*128)   // 17408 rows = 136 tiles of 128

#define ROWB    144                 // 128B of k data + 16B pad
#define TILEB   (128*ROWB)          // 18432 B
#define STAGEB  (2*TILEB)           // A, B = 36864 B
#define SMEMSZ  (2*STAGEB)          // 73728 B -> 2 CTAs/SM

// ---------------- device scratch ----------------
__device__ int   g_cnt[NE], g_cur[NE], g_off[NE + 1];
__device__ int   g_tope[T_TOK * 2];
__device__ float g_topp[T_TOK * 2];
__device__ int   g_rowtok[RCAP];
__device__ float g_roww[RCAP];
__device__ __half g_X [(size_t)RCAP * DIM];
__device__ __half g_S [(size_t)RCAP * HID];
__device__ __half g_Wc[(size_t)NE * 2 * HID * DIM];   // [e][2h+p][d]
__device__ __half g_W3[(size_t)NE * DIM * HID];       // [e][d][h]

// ---------------- host-side streams/events ----------------
struct MoeStreams {
    cudaStream_t s1, s2;
    cudaEvent_t ev0, ev1, ev2;
    MoeStreams() {
        cudaStreamCreateWithFlags(&s1, cudaStreamNonBlocking);
        cudaStreamCreateWithFlags(&s2, cudaStreamNonBlocking);
        cudaEventCreateWithFlags(&ev0, cudaEventDisableTiming);
        cudaEventCreateWithFlags(&ev1, cudaEventDisableTiming);
        cudaEventCreateWithFlags(&ev2, cudaEventDisableTiming);
    }
};
static MoeStreams g_str;

// ---------------- helpers ----------------
__device__ __forceinline__ uint32_t smem_u32(const void* p) {
    uint32_t a;
    asm("{ .reg .u64 t; cvta.to.shared.u64 t, %1; cvt.u32.u64 %0, t; }" : "=r"(a) : "l"(p));
    return a;
}
__device__ __forceinline__ void cp16(uint32_t dst, const void* src) {
    asm volatile("cp.async.cg.shared.global [%0], [%1], 16;" :: "r"(dst), "l"(src));
}
#define CP_COMMIT() asm volatile("cp.async.commit_group;" ::: "memory")
#define CP_WAIT0()  asm volatile("cp.async.wait_group 0;" ::: "memory")

__device__ __forceinline__ void ldsm4(uint32_t* r, uint32_t addr) {
    asm volatile("ldmatrix.sync.aligned.m8n8.x4.shared.b16 {%0,%1,%2,%3}, [%4];"
                 : "=r"(r[0]), "=r"(r[1]), "=r"(r[2]), "=r"(r[3]) : "r"(addr));
}
__device__ __forceinline__ void mma_hf32(float* c, const uint32_t* a, uint32_t b0, uint32_t b1) {
    asm volatile("mma.sync.aligned.m16n8k16.row.col.f32.f16.f16.f32 "
                 "{%0,%1,%2,%3}, {%4,%5,%6,%7}, {%8,%9}, {%0,%1,%2,%3};"
                 : "+f"(c[0]), "+f"(c[1]), "+f"(c[2]), "+f"(c[3])
                 : "r"(a[0]), "r"(a[1]), "r"(a[2]), "r"(a[3]), "r"(b0), "r"(b1));
}
__device__ __forceinline__ void redg_v2(float* p, float a, float b) {
    asm volatile("red.global.add.v2.f32 [%0], {%1, %2};" :: "l"(p), "f"(a), "f"(b) : "memory");
}
__device__ __forceinline__ float swishf(float a) { return a / (1.0f + __expf(-a)); }

// ---------------- routing kernels ----------------
__global__ void k_init0() {
    int i = threadIdx.x;
    if (i < NE) { g_cnt[i] = 0; g_cur[i] = 0; }
}

// gating, float4 both sides: lane handles 4 consecutive d per iteration
__global__ void k_gate(const float* __restrict__ x, const float* __restrict__ Wg) {
    __shared__ __align__(16) float sWgT[NE * DIM];   // [e][d]
    for (int idx = threadIdx.x; idx < DIM * NE; idx += blockDim.x) {
        int d = idx >> 3, e = idx & 7;
        sWgT[e * DIM + d] = Wg[idx];
    }
    __syncthreads();
    int warp = threadIdx.x >> 5, lane = threadIdx.x & 31;
    int t = blockIdx.x * 8 + warp;
    const float4* xr = (const float4*)(x + (size_t)t * DIM);
    float acc[NE];
#pragma unroll
    for (int e = 0; e < NE; e++) acc[e] = 0.0f;
#pragma unroll
    for (int d4 = lane; d4 < DIM / 4; d4 += 32) {
        float4 xv = xr[d4];
#pragma unroll
        for (int e = 0; e < NE; e++) {
            float4 wv = *(const float4*)&sWgT[e * DIM + d4 * 4];
            acc[e] += xv.x * wv.x + xv.y * wv.y + xv.z * wv.z + xv.w * wv.w;
        }
    }
#pragma unroll
    for (int off = 16; off; off >>= 1)
#pragma unroll
        for (int e = 0; e < NE; e++) acc[e] += __shfl_xor_sync(0xffffffffu, acc[e], off);
    if (lane == 0) {
        int e0 = 0; float v0 = acc[0];
#pragma unroll
        for (int e = 1; e < NE; e++) if (acc[e] > v0) { v0 = acc[e]; e0 = e; }
        int e1 = -1; float v1 = -1e30f;
#pragma unroll
        for (int e = 0; e < NE; e++) if (e != e0 && acc[e] > v1) { v1 = acc[e]; e1 = e; }
        float ex = __expf(v1 - v0);
        g_tope[t * 2 + 0] = e0; g_topp[t * 2 + 0] = 1.0f / (1.0f + ex);
        g_tope[t * 2 + 1] = e1; g_topp[t * 2 + 1] = ex / (1.0f + ex);
        atomicAdd(&g_cnt[e0], 1);
        atomicAdd(&g_cnt[e1], 1);
    }
}

__global__ void k_offsets() {
    if (threadIdx.x == 0) {
        int o = 0;
#pragma unroll
        for (int e = 0; e < NE; e++) {
            g_off[e] = o;
            o += ((g_cnt[e] + 127) / 128) * 128;
        }
        g_off[NE] = o;
    }
}

// fused scatter + gather: one block per (token, k) slot
__global__ __launch_bounds__(128) void k_route(const float* __restrict__ x) {
    __shared__ int spos;
    int i = blockIdx.x;
    int tid = threadIdx.x;
    if (tid == 0) {
        int e = g_tope[i];
        int pos = g_off[e] + atomicAdd(&g_cur[e], 1);
        g_rowtok[pos] = i >> 1;
        g_roww[pos] = g_topp[i];
        spos = pos;
    }
    __syncthreads();
    int pos = spos;
    int t = i >> 1;
    const float4* src = (const float4*)(x + (size_t)t * DIM);
    float4 v0 = src[tid * 2], v1 = src[tid * 2 + 1];
    __half2 a = __floats2half2_rn(v0.x, v0.y);
    __half2 b = __floats2half2_rn(v0.z, v0.w);
    __half2 c = __floats2half2_rn(v1.x, v1.y);
    __half2 d = __floats2half2_rn(v1.z, v1.w);
    *(uint4*)(g_X + (size_t)pos * DIM + tid * 8) =
        make_uint4(*(unsigned*)&a, *(unsigned*)&b, *(unsigned*)&c, *(unsigned*)&d);
}

// W1 and W2 [e][d][h] -> Wc [e][2h+p][d] (fp16), fused
__global__ void k_tr12f(const float* __restrict__ W1, const float* __restrict__ W2) {
    __shared__ float t[32][33];
    int e = blockIdx.z;
    int h0 = blockIdx.x * 32, d0 = blockIdx.y * 32;
    int tx = threadIdx.x, ty = threadIdx.y;
#pragma unroll
    for (int p = 0; p < 2; p++) {
        const float* s = (p == 0 ? W1 : W2) + (size_t)e * DIM * HID;
        __syncthreads();
#pragma unroll
        for (int i = ty; i < 32; i += 8)
            t[i][tx] = s[(size_t)(d0 + i) * HID + h0 + tx];
        __syncthreads();
#pragma unroll
        for (int i = ty; i < 32; i += 8) {
            float v = t[tx][i];
            int n = 2 * (h0 + i) + p;
            g_Wc[((size_t)e * 2 * HID + n) * DIM + d0 + tx] = __float2half_rn(v);
        }
    }
}

// W3 [e][h][d] -> W3T [e][d][h]
__global__ void k_tr3(const float* __restrict__ src) {
    __shared__ float t[32][33];
    int e = blockIdx.z;
    const float* s = src + (size_t)e * HID * DIM;
    int d0 = blockIdx.x * 32, h0 = blockIdx.y * 32;
    int tx = threadIdx.x, ty = threadIdx.y;
#pragma unroll
    for (int i = ty; i < 32; i += 8)
        t[i][tx] = s[(size_t)(h0 + i) * DIM + d0 + tx];
    __syncthreads();
#pragma unroll
    for (int i = ty; i < 32; i += 8) {
        float v = t[tx][i];
        g_W3[((size_t)e * DIM + d0 + i) * HID + h0 + tx] = __float2half_rn(v);
    }
}

// ---------------- stage loader: 128 threads, 16 cp16 each (BK=64) ----------------
__device__ __forceinline__ void load_stage(
    uint32_t st, int tid, int k0, int kstride, const __half* A, const __half* B)
{
#pragma unroll
    for (int rep = 0; rep < 8; rep++) {
        int c = tid + rep * 128;
        int row = c >> 3, kc = c & 7;
        uint32_t doff = row * ROWB + kc * 16;
        size_t goff = (size_t)row * kstride + k0 + kc * 8;
        cp16(st + doff,         A + goff);
        cp16(st + TILEB + doff, B + goff);
    }
    CP_COMMIT();
}

// compute one BK=64 stage, warptile 64x64
__device__ __forceinline__ void compute_stage(
    uint32_t st, int warpM, int warpN, int lane, float acc[4][8][4])
{
    int mlane = lane & 7;
    int mid = lane >> 3;
#pragma unroll
    for (int ks = 0; ks < 4; ks++) {
        uint32_t b[4][4];
#pragma unroll
        for (int nj = 0; nj < 4; nj++) {
            int row = warpN * 64 + nj * 16 + ((mid >> 1) << 3) + mlane;
            int colB = ks * 32 + ((mid & 1) << 4);
            ldsm4(b[nj], st + TILEB + row * ROWB + colB);
        }
#pragma unroll
        for (int mi = 0; mi < 4; mi++) {
            uint32_t a[4];
            int row = warpM * 64 + mi * 16 + ((mid & 1) << 3) + mlane;
            int colB = ks * 32 + ((mid >> 1) << 4);
            ldsm4(a, st + row * ROWB + colB);
#pragma unroll
            for (int nj = 0; nj < 4; nj++)
#pragma unroll
                for (int tt = 0; tt < 2; tt++)
                    mma_hf32(acc[mi][nj * 2 + tt], a, b[nj][tt * 2], b[nj][tt * 2 + 1]);
        }
    }
}

#define GEMM_MAINLOOP(NC, KSTRIDE)                                                  \
    load_stage(sb, tid, 0, KSTRIDE, Ap, Bp);                                        \
    for (int c = 0; c < (NC); c++) {                                                \
        CP_WAIT0();                                                                 \
        __syncthreads();                                                            \
        if (c + 1 < (NC))                                                           \
            load_stage(sb + ((c + 1) & 1) * STAGEB, tid, (c + 1) * BK, KSTRIDE,     \
                       Ap, Bp);                                                     \
        compute_stage(sb + (c & 1) * STAGEB, warpM, warpN, lane, acc);              \
    }

// ---------------- GEMM1: [RCAP,4096] = X @ Wc, epilogue SwiGLU -> S ----------------
__global__ __launch_bounds__(128, 2) void k_gemm1() {
    int row0 = blockIdx.y * BM;
    int e = 0;
#pragma unroll
    for (int i = 1; i < NE; i++) if (g_off[i] <= row0) e = i;
    if (g_cnt[e] - (row0 - g_off[e]) <= 0) return;

    extern __shared__ __align__(128) char smem[];
    uint32_t sb = smem_u32(smem);
    int tid = threadIdx.x, wid = tid >> 5, lane = tid & 31;
    int warpM = wid >> 1, warpN = wid & 1;
    int n0 = blockIdx.x * BN;

    const __half* Ap = g_X  + (size_t)row0 * DIM;
    const __half* Bp = g_Wc + (size_t)e * 2 * HID * DIM + (size_t)n0 * DIM;

    float acc[4][8][4];
#pragma unroll
    for (int a = 0; a < 4; a++)
#pragma unroll
        for (int b = 0; b < 8; b++)
#pragma unroll
            for (int c = 0; c < 4; c++) acc[a][b][c] = 0.0f;

    GEMM_MAINLOOP(DIM / BK, DIM)

    __syncthreads();
    char* stg = smem + wid * 2048;
    int qrow = lane >> 2, qcol = lane & 3;
    int jgb = (n0 >> 1) + warpN * 32;
#pragma unroll
    for (int mi = 0; mi < 4; mi++) {
        int r0 = row0 + warpM * 64 + mi * 16;
#pragma unroll
        for (int ni = 0; ni < 8; ni++) {
            int col = ni * 4 + qcol;
            float v0 = swishf(acc[mi][ni][0]) * acc[mi][ni][1];
            float v1 = swishf(acc[mi][ni][2]) * acc[mi][ni][3];
            *(__half*)(stg + qrow * 80 + col * 2) = __float2half_rn(v0);
            *(__half*)(stg + (qrow + 8) * 80 + col * 2) = __float2half_rn(v1);
        }
        __syncwarp();
#pragma unroll
        for (int k = 0; k < 2; k++) {
            int chunk = lane + 32 * k;
            int row = chunk >> 2, part = chunk & 3;
            uint4 vh = *(uint4*)(stg + row * 80 + part * 16);
            size_t o = (size_t)(r0 + row) * HID + jgb + part * 8;
            *(uint4*)(g_S + o) = vh;
        }
        __syncwarp();
    }
}

// ---------------- GEMM2: out[t] += w * (S @ W3T) ----------------
__global__ __launch_bounds__(128, 2) void k_gemm2(float* __restrict__ out) {
    int row0 = blockIdx.y * BM;
    int e = 0;
#pragma unroll
    for (int i = 1; i < NE; i++) if (g_off[i] <= row0) e = i;
    if (g_cnt[e] - (row0 - g_off[e]) <= 0) return;

    extern __shared__ __align__(128) char smem[];
    uint32_t sb = smem_u32(smem);
    int tid = threadIdx.x, wid = tid >> 5, lane = tid & 31;
    int warpM = wid >> 1, warpN = wid & 1;
    int n0 = blockIdx.x * BN;

    const __half* Ap = g_S  + (size_t)row0 * HID;
    const __half* Bp = g_W3 + (size_t)e * DIM * HID + (size_t)n0 * HID;

    float acc[4][8][4];
#pragma unroll
    for (int a = 0; a < 4; a++)
#pragma unroll
        for (int b = 0; b < 8; b++)
#pragma unroll
            for (int c = 0; c < 4; c++) acc[a][b][c] = 0.0f;

    GEMM_MAINLOOP(HID / BK, HID)

    int qrow = lane >> 2, qcol = lane & 3;
#pragma unroll
    for (int mi = 0; mi < 4; mi++) {
        int rbase = row0 + warpM * 64 + mi * 16 + qrow;
#pragma unroll
        for (int half = 0; half < 2; half++) {
            int r = rbase + half * 8;
            int t = g_rowtok[r];
            if (t < 0) continue;
            float wgt = g_roww[r];
            float* orow = out + (size_t)t * DIM;
#pragma unroll
            for (int ni = 0; ni < 8; ni++) {
                int colg = n0 + warpN * 64 + ni * 8 + qcol * 2;
                redg_v2(orow + colg, wgt * acc[mi][ni][half * 2],
                                     wgt * acc[mi][ni][half * 2 + 1]);
            }
        }
    }
}

// ---------------- launch ----------------
extern "C" void kernel_launch(void* const* d_in, const int* in_sizes, int n_in,
                              void* d_out, int out_size) {
    const float* x  = (const float*)d_in[0];
    const float* Wg = (const float*)d_in[1];
    const float* W1 = (const float*)d_in[2];
    const float* W2 = (const float*)d_in[3];
    const float* W3 = (const float*)d_in[4];
    float* out = (float*)d_out;

    cudaFuncSetAttribute(k_gemm1, cudaFuncAttributeMaxDynamicSharedMemorySize, SMEMSZ);
    cudaFuncSetAttribute(k_gemm2, cudaFuncAttributeMaxDynamicSharedMemorySize, SMEMSZ);

    void *pX = nullptr, *pRT = nullptr;
    cudaGetSymbolAddress(&pX, g_X);
    cudaGetSymbolAddress(&pRT, g_rowtok);

    // fork side streams off the main (captured) stream
    cudaEventRecord(g_str.ev0, 0);
    cudaStreamWaitEvent(g_str.s1, g_str.ev0, 0);
    cudaStreamWaitEvent(g_str.s2, g_str.ev0, 0);

    // s1: W1/W2 conversion (largest independent chunk)
    k_tr12f<<<dim3(HID / 32, DIM / 32, NE), dim3(32, 8), 0, g_str.s1>>>(W1, W2);
    cudaEventRecord(g_str.ev1, g_str.s1);

    // s2: memsets + W3 conversion
    cudaMemsetAsync(out, 0, (size_t)T_TOK * DIM * sizeof(float), g_str.s2);
    cudaMemsetAsync(pX, 0, (size_t)RCAP * DIM * sizeof(__half), g_str.s2);
    cudaMemsetAsync(pRT, 0xFF, (size_t)RCAP * sizeof(int), g_str.s2);
    k_tr3<<<dim3(DIM / 32, HID / 32, NE), dim3(32, 8), 0, g_str.s2>>>(W3);
    cudaEventRecord(g_str.ev2, g_str.s2);

    // main stream: routing chain
    k_init0<<<1, 32>>>();
    k_gate<<<T_TOK / 8, 256>>>(x, Wg);
    k_offsets<<<1, 32>>>();
    cudaStreamWaitEvent(0, g_str.ev2, 0);   // g_X / rowtok / out / W3 ready
    k_route<<<T_TOK * 2, 128>>>(x);
    cudaStreamWaitEvent(0, g_str.ev1, 0);   // Wc ready

    k_gemm1<<<dim3(2 * HID / BN, RCAP / BM), 128, SMEMSZ>>>();
    k_gemm2<<<dim3(DIM / BN, RCAP / BM), 128, SMEMSZ>>>(out);
}

// round 17
// speedup vs baseline: 1.0810x; 1.0810x over previous
#include <cuda_runtime.h>
#include <cuda_fp16.h>
#include <cstdint>

#define T_TOK 8192
#define DIM   1024
#define HID   2048
#define NE    8
#define BM    128
#define BN    128
#define BK    64
#define RCAP  (T_TOK*2 + NE*128)   // 17408 rows = 136 tiles of 128

#define ROWB    144                 // 128B of k data + 16B pad
#define TILEB   (128*ROWB)          // 18432 B
#define STAGEB  (2*TILEB)           // A, B = 36864 B
#define SMEMSZ  (2*STAGEB + 512)    // + token table -> 74240 B, 2 CTAs/SM

// ---------------- device scratch ----------------
__device__ int   g_cnt[NE], g_cur[NE], g_off[NE + 1];
__device__ int   g_tope[T_TOK * 2];
__device__ float g_topp[T_TOK * 2];
__device__ int   g_rowtok[RCAP];
__device__ float g_roww[RCAP];
__device__ __half g_Xh[(size_t)T_TOK * DIM];          // fp16(x), token order
__device__ __half g_S [(size_t)RCAP * HID];
__device__ __half g_Wc[(size_t)NE * 2 * HID * DIM];   // [e][2h+p][d]
__device__ __half g_W3[(size_t)NE * DIM * HID];       // [e][d][h]

// ---------------- host-side streams/events ----------------
struct MoeStreams {
    cudaStream_t s1, s2;
    cudaEvent_t ev0, ev1, ev2;
    MoeStreams() {
        cudaStreamCreateWithFlags(&s1, cudaStreamNonBlocking);
        cudaStreamCreateWithFlags(&s2, cudaStreamNonBlocking);
        cudaEventCreateWithFlags(&ev0, cudaEventDisableTiming);
        cudaEventCreateWithFlags(&ev1, cudaEventDisableTiming);
        cudaEventCreateWithFlags(&ev2, cudaEventDisableTiming);
    }
};
static MoeStreams g_str;

// ---------------- helpers ----------------
__device__ __forceinline__ uint32_t smem_u32(const void* p) {
    uint32_t a;
    asm("{ .reg .u64 t; cvta.to.shared.u64 t, %1; cvt.u32.u64 %0, t; }" : "=r"(a) : "l"(p));
    return a;
}
__device__ __forceinline__ void cp16(uint32_t dst, const void* src) {
    asm volatile("cp.async.cg.shared.global [%0], [%1], 16;" :: "r"(dst), "l"(src));
}
// zero-fill variant: srcsize=0 -> no global read, smem gets zeros
__device__ __forceinline__ void cp16z(uint32_t dst, const void* src, int srcsize) {
    asm volatile("cp.async.cg.shared.global [%0], [%1], 16, %2;"
                 :: "r"(dst), "l"(src), "r"(srcsize));
}
#define CP_COMMIT() asm volatile("cp.async.commit_group;" ::: "memory")
#define CP_WAIT0()  asm volatile("cp.async.wait_group 0;" ::: "memory")

__device__ __forceinline__ void ldsm4(uint32_t* r, uint32_t addr) {
    asm volatile("ldmatrix.sync.aligned.m8n8.x4.shared.b16 {%0,%1,%2,%3}, [%4];"
                 : "=r"(r[0]), "=r"(r[1]), "=r"(r[2]), "=r"(r[3]) : "r"(addr));
}
__device__ __forceinline__ void mma_hf32(float* c, const uint32_t* a, uint32_t b0, uint32_t b1) {
    asm volatile("mma.sync.aligned.m16n8k16.row.col.f32.f16.f16.f32 "
                 "{%0,%1,%2,%3}, {%4,%5,%6,%7}, {%8,%9}, {%0,%1,%2,%3};"
                 : "+f"(c[0]), "+f"(c[1]), "+f"(c[2]), "+f"(c[3])
                 : "r"(a[0]), "r"(a[1]), "r"(a[2]), "r"(a[3]), "r"(b0), "r"(b1));
}
__device__ __forceinline__ void redg_v2(float* p, float a, float b) {
    asm volatile("red.global.add.v2.f32 [%0], {%1, %2};" :: "l"(p), "f"(a), "f"(b) : "memory");
}
__device__ __forceinline__ float swishf(float a) { return a / (1.0f + __expf(-a)); }

// ---------------- routing kernels ----------------
__global__ void k_init0() {
    int i = threadIdx.x;
    if (i < NE) { g_cnt[i] = 0; g_cur[i] = 0; }
}

// gating + fp16 conversion of x (token order)
__global__ void k_gate(const float* __restrict__ x, const float* __restrict__ Wg) {
    __shared__ __align__(16) float sWgT[NE * DIM];   // [e][d]
    for (int idx = threadIdx.x; idx < DIM * NE; idx += blockDim.x) {
        int d = idx >> 3, e = idx & 7;
        sWgT[e * DIM + d] = Wg[idx];
    }
    __syncthreads();
    int warp = threadIdx.x >> 5, lane = threadIdx.x & 31;
    int t = blockIdx.x * 8 + warp;
    const float4* xr = (const float4*)(x + (size_t)t * DIM);
    float acc[NE];
#pragma unroll
    for (int e = 0; e < NE; e++) acc[e] = 0.0f;
#pragma unroll
    for (int d4 = lane; d4 < DIM / 4; d4 += 32) {
        float4 xv = xr[d4];
        __half2 h0 = __floats2half2_rn(xv.x, xv.y);
        __half2 h1 = __floats2half2_rn(xv.z, xv.w);
        *(uint2*)(g_Xh + (size_t)t * DIM + d4 * 4) =
            make_uint2(*(unsigned*)&h0, *(unsigned*)&h1);
#pragma unroll
        for (int e = 0; e < NE; e++) {
            float4 wv = *(const float4*)&sWgT[e * DIM + d4 * 4];
            acc[e] += xv.x * wv.x + xv.y * wv.y + xv.z * wv.z + xv.w * wv.w;
        }
    }
#pragma unroll
    for (int off = 16; off; off >>= 1)
#pragma unroll
        for (int e = 0; e < NE; e++) acc[e] += __shfl_xor_sync(0xffffffffu, acc[e], off);
    if (lane == 0) {
        int e0 = 0; float v0 = acc[0];
#pragma unroll
        for (int e = 1; e < NE; e++) if (acc[e] > v0) { v0 = acc[e]; e0 = e; }
        int e1 = -1; float v1 = -1e30f;
#pragma unroll
        for (int e = 0; e < NE; e++) if (e != e0 && acc[e] > v1) { v1 = acc[e]; e1 = e; }
        float ex = __expf(v1 - v0);
        g_tope[t * 2 + 0] = e0; g_topp[t * 2 + 0] = 1.0f / (1.0f + ex);
        g_tope[t * 2 + 1] = e1; g_topp[t * 2 + 1] = ex / (1.0f + ex);
        atomicAdd(&g_cnt[e0], 1);
        atomicAdd(&g_cnt[e1], 1);
    }
}

__global__ void k_offsets() {
    if (threadIdx.x == 0) {
        int o = 0;
#pragma unroll
        for (int e = 0; e < NE; e++) {
            g_off[e] = o;
            o += ((g_cnt[e] + 127) / 128) * 128;
        }
        g_off[NE] = o;
    }
}

__global__ void k_scatter() {
    int i = blockIdx.x * blockDim.x + threadIdx.x;
    if (i >= T_TOK * 2) return;
    int e = g_tope[i];
    int pos = g_off[e] + atomicAdd(&g_cur[e], 1);
    g_rowtok[pos] = i >> 1;
    g_roww[pos] = g_topp[i];
}

// W1 and W2 [e][d][h] -> Wc [e][2h+p][d] (fp16), fused
__global__ void k_tr12f(const float* __restrict__ W1, const float* __restrict__ W2) {
    __shared__ float t[32][33];
    int e = blockIdx.z;
    int h0 = blockIdx.x * 32, d0 = blockIdx.y * 32;
    int tx = threadIdx.x, ty = threadIdx.y;
#pragma unroll
    for (int p = 0; p < 2; p++) {
        const float* s = (p == 0 ? W1 : W2) + (size_t)e * DIM * HID;
        __syncthreads();
#pragma unroll
        for (int i = ty; i < 32; i += 8)
            t[i][tx] = s[(size_t)(d0 + i) * HID + h0 + tx];
        __syncthreads();
#pragma unroll
        for (int i = ty; i < 32; i += 8) {
            float v = t[tx][i];
            int n = 2 * (h0 + i) + p;
            g_Wc[((size_t)e * 2 * HID + n) * DIM + d0 + tx] = __float2half_rn(v);
        }
    }
}

// W3 [e][h][d] -> W3T [e][d][h]
__global__ void k_tr3(const float* __restrict__ src) {
    __shared__ float t[32][33];
    int e = blockIdx.z;
    const float* s = src + (size_t)e * HID * DIM;
    int d0 = blockIdx.x * 32, h0 = blockIdx.y * 32;
    int tx = threadIdx.x, ty = threadIdx.y;
#pragma unroll
    for (int i = ty; i < 32; i += 8)
        t[i][tx] = s[(size_t)(h0 + i) * DIM + d0 + tx];
    __syncthreads();
#pragma unroll
    for (int i = ty; i < 32; i += 8) {
        float v = t[tx][i];
        g_W3[((size_t)e * DIM + d0 + i) * HID + h0 + tx] = __float2half_rn(v);
    }
}

// ---------------- GEMM stage loaders ----------------
// GEMM1 A: gather rows from g_Xh via smem token table; pad rows zero-filled
__device__ __forceinline__ void load_stage1(
    uint32_t st, int tid, int k0, const int* sTok, const __half* Bp)
{
#pragma unroll
    for (int rep = 0; rep < 8; rep++) {
        int c = tid + rep * 128;
        int row = c >> 3, kc = c & 7;
        uint32_t doff = row * ROWB + kc * 16;
        int t = sTok[row];
        int tt = t < 0 ? 0 : t;
        int sz = t < 0 ? 0 : 16;
        cp16z(st + doff, g_Xh + (size_t)tt * DIM + k0 + kc * 8, sz);
        cp16(st + TILEB + doff, Bp + (size_t)row * DIM + k0 + kc * 8);
    }
    CP_COMMIT();
}

__device__ __forceinline__ void load_stage2(
    uint32_t st, int tid, int k0, const __half* Ap, const __half* Bp)
{
#pragma unroll
    for (int rep = 0; rep < 8; rep++) {
        int c = tid + rep * 128;
        int row = c >> 3, kc = c & 7;
        uint32_t doff = row * ROWB + kc * 16;
        size_t goff = (size_t)row * HID + k0 + kc * 8;
        cp16(st + doff,         Ap + goff);
        cp16(st + TILEB + doff, Bp + goff);
    }
    CP_COMMIT();
}

// compute one BK=64 stage, warptile 64x64
__device__ __forceinline__ void compute_stage(
    uint32_t st, int warpM, int warpN, int lane, float acc[4][8][4])
{
    int mlane = lane & 7;
    int mid = lane >> 3;
#pragma unroll
    for (int ks = 0; ks < 4; ks++) {
        uint32_t b[4][4];
#pragma unroll
        for (int nj = 0; nj < 4; nj++) {
            int row = warpN * 64 + nj * 16 + ((mid >> 1) << 3) + mlane;
            int colB = ks * 32 + ((mid & 1) << 4);
            ldsm4(b[nj], st + TILEB + row * ROWB + colB);
        }
#pragma unroll
        for (int mi = 0; mi < 4; mi++) {
            uint32_t a[4];
            int row = warpM * 64 + mi * 16 + ((mid & 1) << 3) + mlane;
            int colB = ks * 32 + ((mid >> 1) << 4);
            ldsm4(a, st + row * ROWB + colB);
#pragma unroll
            for (int nj = 0; nj < 4; nj++)
#pragma unroll
                for (int tt = 0; tt < 2; tt++)
                    mma_hf32(acc[mi][nj * 2 + tt], a, b[nj][tt * 2], b[nj][tt * 2 + 1]);
        }
    }
}

// ---------------- GEMM1: [RCAP,4096] = gather(Xh) @ Wc, epilogue SwiGLU -> S ----------------
__global__ __launch_bounds__(128, 2) void k_gemm1() {
    int row0 = blockIdx.y * BM;
    int e = 0;
#pragma unroll
    for (int i = 1; i < NE; i++) if (g_off[i] <= row0) e = i;
    if (g_cnt[e] - (row0 - g_off[e]) <= 0) return;

    extern __shared__ __align__(128) char smem[];
    uint32_t sb = smem_u32(smem);
    int tid = threadIdx.x, wid = tid >> 5, lane = tid & 31;
    int warpM = wid >> 1, warpN = wid & 1;
    int n0 = blockIdx.x * BN;

    int* sTok = (int*)(smem + 2 * STAGEB);
    if (tid < 128) sTok[tid] = g_rowtok[row0 + tid];
    __syncthreads();

    const __half* Bp = g_Wc + (size_t)e * 2 * HID * DIM + (size_t)n0 * DIM;

    float acc[4][8][4];
#pragma unroll
    for (int a = 0; a < 4; a++)
#pragma unroll
        for (int b = 0; b < 8; b++)
#pragma unroll
            for (int c = 0; c < 4; c++) acc[a][b][c] = 0.0f;

    load_stage1(sb, tid, 0, sTok, Bp);
    const int NC = DIM / BK;
    for (int c = 0; c < NC; c++) {
        CP_WAIT0();
        __syncthreads();
        if (c + 1 < NC)
            load_stage1(sb + ((c + 1) & 1) * STAGEB, tid, (c + 1) * BK, sTok, Bp);
        compute_stage(sb + (c & 1) * STAGEB, warpM, warpN, lane, acc);
    }

    __syncthreads();
    char* stg = smem + wid * 2048;
    int qrow = lane >> 2, qcol = lane & 3;
    int jgb = (n0 >> 1) + warpN * 32;
#pragma unroll
    for (int mi = 0; mi < 4; mi++) {
        int r0 = row0 + warpM * 64 + mi * 16;
#pragma unroll
        for (int ni = 0; ni < 8; ni++) {
            int col = ni * 4 + qcol;
            float v0 = swishf(acc[mi][ni][0]) * acc[mi][ni][1];
            float v1 = swishf(acc[mi][ni][2]) * acc[mi][ni][3];
            *(__half*)(stg + qrow * 80 + col * 2) = __float2half_rn(v0);
            *(__half*)(stg + (qrow + 8) * 80 + col * 2) = __float2half_rn(v1);
        }
        __syncwarp();
#pragma unroll
        for (int k = 0; k < 2; k++) {
            int chunk = lane + 32 * k;
            int row = chunk >> 2, part = chunk & 3;
            uint4 vh = *(uint4*)(stg + row * 80 + part * 16);
            size_t o = (size_t)(r0 + row) * HID + jgb + part * 8;
            *(uint4*)(g_S + o) = vh;
        }
        __syncwarp();
    }
}

// ---------------- GEMM2: out[t] += w * (S @ W3T) ----------------
__global__ __launch_bounds__(128, 2) void k_gemm2(float* __restrict__ out) {
    int row0 = blockIdx.y * BM;
    int e = 0;
#pragma unroll
    for (int i = 1; i < NE; i++) if (g_off[i] <= row0) e = i;
    if (g_cnt[e] - (row0 - g_off[e]) <= 0) return;

    extern __shared__ __align__(128) char smem[];
    uint32_t sb = smem_u32(smem);
    int tid = threadIdx.x, wid = tid >> 5, lane = tid & 31;
    int warpM = wid >> 1, warpN = wid & 1;
    int n0 = blockIdx.x * BN;

    const __half* Ap = g_S  + (size_t)row0 * HID;
    const __half* Bp = g_W3 + (size_t)e * DIM * HID + (size_t)n0 * HID;

    float acc[4][8][4];
#pragma unroll
    for (int a = 0; a < 4; a++)
#pragma unroll
        for (int b = 0; b < 8; b++)
#pragma unroll
            for (int c = 0; c < 4; c++) acc[a][b][c] = 0.0f;

    load_stage2(sb, tid, 0, Ap, Bp);
    const int NC = HID / BK;
    for (int c = 0; c < NC; c++) {
        CP_WAIT0();
        __syncthreads();
        if (c + 1 < NC)
            load_stage2(sb + ((c + 1) & 1) * STAGEB, tid, (c + 1) * BK, Ap, Bp);
        compute_stage(sb + (c & 1) * STAGEB, warpM, warpN, lane, acc);
    }

    int qrow = lane >> 2, qcol = lane & 3;
#pragma unroll
    for (int mi = 0; mi < 4; mi++) {
        int rbase = row0 + warpM * 64 + mi * 16 + qrow;
#pragma unroll
        for (int half = 0; half < 2; half++) {
            int r = rbase + half * 8;
            int t = g_rowtok[r];
            if (t < 0) continue;
            float wgt = g_roww[r];
            float* orow = out + (size_t)t * DIM;
#pragma unroll
            for (int ni = 0; ni < 8; ni++) {
                int colg = n0 + warpN * 64 + ni * 8 + qcol * 2;
                redg_v2(orow + colg, wgt * acc[mi][ni][half * 2],
                                     wgt * acc[mi][ni][half * 2 + 1]);
            }
        }
    }
}

// ---------------- launch ----------------
extern "C" void kernel_launch(void* const* d_in, const int* in_sizes, int n_in,
                              void* d_out, int out_size) {
    const float* x  = (const float*)d_in[0];
    const float* Wg = (const float*)d_in[1];
    const float* W1 = (const float*)d_in[2];
    const float* W2 = (const float*)d_in[3];
    const float* W3 = (const float*)d_in[4];
    float* out = (float*)d_out;

    cudaFuncSetAttribute(k_gemm1, cudaFuncAttributeMaxDynamicSharedMemorySize, SMEMSZ);
    cudaFuncSetAttribute(k_gemm2, cudaFuncAttributeMaxDynamicSharedMemorySize, SMEMSZ);

    void* pRT = nullptr;
    cudaGetSymbolAddress(&pRT, g_rowtok);

    // fork side streams off the main (captured) stream
    cudaEventRecord(g_str.ev0, 0);
    cudaStreamWaitEvent(g_str.s1, g_str.ev0, 0);
    cudaStreamWaitEvent(g_str.s2, g_str.ev0, 0);

    // s1: W1/W2 conversion
    k_tr12f<<<dim3(HID / 32, DIM / 32, NE), dim3(32, 8), 0, g_str.s1>>>(W1, W2);
    cudaEventRecord(g_str.ev1, g_str.s1);

    // s2: memsets + W3 conversion
    cudaMemsetAsync(out, 0, (size_t)T_TOK * DIM * sizeof(float), g_str.s2);
    cudaMemsetAsync(pRT, 0xFF, (size_t)RCAP * sizeof(int), g_str.s2);
    k_tr3<<<dim3(DIM / 32, HID / 32, NE), dim3(32, 8), 0, g_str.s2>>>(W3);
    cudaEventRecord(g_str.ev2, g_str.s2);

    // main stream: routing chain (gate also emits fp16 x)
    k_init0<<<1, 32>>>();
    k_gate<<<T_TOK / 8, 256>>>(x, Wg);
    k_offsets<<<1, 32>>>();
    cudaStreamWaitEvent(0, g_str.ev2, 0);   // rowtok memset / out ready
    k_scatter<<<(T_TOK * 2 + 255) / 256, 256>>>();
    cudaStreamWaitEvent(0, g_str.ev1, 0);   // Wc ready

    k_gemm1<<<dim3(2 * HID / BN, RCAP / BM), 128, SMEMSZ>>>();
    k_gemm2<<<dim3(DIM / BN, RCAP / BM), 128, SMEMSZ>>>(out);
}